// round 15
// baseline (speedup 1.0000x reference)
#include <cuda_runtime.h>
#include <cuda_fp16.h>
#include <math.h>

// Problem dims (fixed by reference setup_inputs)
#define BB 64
#define FF 128
#define TT 4096
#define KK 13
#define NN (BB*TT)     // 262144 samples per coefficient
#define T2W (TT/2)     // float2 units along T

#define GRID1 256      // persistent grid: must be <= co-resident capacity (296)
#define SPB   1024     // samples per block (2 per thread, 512 threads)

// ---- device scratch (static: no allocation allowed; zero-init at load) ----
__device__ double   g_sum[2][KK];
__device__ double   g_sumsq[2][KK];
__device__ double   g_mcd_acc;
__device__ unsigned g_arrive;
__device__ unsigned g_depart;

// ---- packed fp32x2 helpers (Blackwell FFMA2 via PTX) ----
__device__ __forceinline__ unsigned long long pack2(float x, float y) {
    unsigned long long r;
    asm("mov.b64 %0, {%1, %2};" : "=l"(r) : "f"(x), "f"(y));
    return r;
}
__device__ __forceinline__ void unpack2(unsigned long long v, float& x, float& y) {
    asm("mov.b64 {%0, %1}, %2;" : "=f"(x), "=f"(y) : "l"(v));
}
__device__ __forceinline__ void fma2(unsigned long long& a,
                                     unsigned long long w,
                                     unsigned long long v) {
    asm("fma.rn.f32x2 %0, %1, %2, %0;" : "+l"(a) : "l"(w), "l"(v));
}

// Dynamic smem layout:
//   [0, 6656)        float2 basis[KK][64]   ({w,w} pairs, ln2+scale folded)
//   [6656, 59904)    __half cep[2][KK][SPB] (per-block cepstra, both tensors)
#define SMEM_BASIS 0
#define SMEM_CEP   6656
#define SMEM_TOTAL 59904

// ---------------------------------------------------------------------------
// Persistent fused kernel (512 threads, 2 samples/thread for low regs + 32
// warps/SM on doubly-occupied SMs):
//  phase 1: log2(1+|x|) -> folded 13-pt DCT (f32x2 FMAs) for both tensors,
//           cepstra -> SMEM (fp16), stats -> global double atomics
//  grid barrier (arrive counter + spin; grid fully co-resident)
//  phase 2: finalize mean/rstd per block, MCD from SMEM cepstra, last block
//           writes the scalar and resets all global state for graph replay.
// Block bx: b = bx>>2, t-chunk = bx&3. Thread owns 2 adjacent t (float2).
// ---------------------------------------------------------------------------
__global__ __launch_bounds__(512, 2) void mcd_fused(const float* __restrict__ xt,
                                                    const float* __restrict__ xp,
                                                    float* __restrict__ out) {
    extern __shared__ char dsm[];
    float2* sbasis = (float2*)(dsm + SMEM_BASIS);          // [KK][64]
    __half* cep    = (__half*)(dsm + SMEM_CEP);            // [2][KK][SPB]

    __shared__ float shS[2][KK], shQ[2][KK];
    __shared__ float srT[KK], srP[KK], soff[KK];
    __shared__ float sh_acc;

    const int tid = threadIdx.x;

    // build basis: {w,w} duplicated, dct scale and ln2 folded in
    for (int i = tid; i < KK * 64; i += blockDim.x) {
        int k = i >> 6, f = i & 63;
        float scale = (k == 0) ? 0.088388347648318447f : 0.125f;
        float w = cospif((float)((2*f + 1) * k) * (1.0f/256.0f))
                * scale * 0.69314718055994531f;
        sbasis[i] = make_float2(w, w);
    }
    if (tid < 2 * KK) {
        ((float*)shS)[tid] = 0.f;
        ((float*)shQ)[tid] = 0.f;
    }
    if (tid == 0) sh_acc = 0.f;
    __syncthreads();

    const int b  = blockIdx.x >> 2;
    const int tc = blockIdx.x & 3;
    const int t2 = tc * 512 + tid;          // float2 index along T
    const int lane = tid & 31;

    // ---------------- phase 1: DCT + stats, cepstra to smem ----------------
#pragma unroll 1
    for (int z = 0; z < 2; z++) {
        const float* src = z ? xp : xt;
        const float2* px = (const float2*)(src + (size_t)b * FF * TT) + t2;

        unsigned long long acc[KK];   // packed (c_lo, c_hi) fp32 pairs
#pragma unroll
        for (int k = 0; k < KK; k++) acc[k] = 0ull;

        const int PF = 4;
        float2 bl[PF], bh[PF];
#pragma unroll
        for (int j = 0; j < PF; j++) {
            bl[j] = __ldcs(px + (size_t)j * T2W);
            bh[j] = __ldcs(px + (size_t)(FF-1-j) * T2W);
        }

#pragma unroll 1
        for (int f0 = 0; f0 < 64; f0 += PF) {
            float2 cl[PF], ch[PF];
#pragma unroll
            for (int j = 0; j < PF; j++) { cl[j] = bl[j]; ch[j] = bh[j]; }
            if (f0 + PF < 64) {
#pragma unroll
                for (int j = 0; j < PF; j++) {
                    bl[j] = __ldcs(px + (size_t)(f0 + PF + j) * T2W);
                    bh[j] = __ldcs(px + (size_t)(FF-1 - (f0 + PF + j)) * T2W);
                }
            }
#pragma unroll
            for (int j = 0; j < PF; j++) {
                float l0 = __log2f(1.0f + fabsf(cl[j].x));
                float l1 = __log2f(1.0f + fabsf(cl[j].y));
                float h0 = __log2f(1.0f + fabsf(ch[j].x));
                float h1 = __log2f(1.0f + fabsf(ch[j].y));
                unsigned long long vs = pack2(l0 + h0, l1 + h1);
                unsigned long long vd = pack2(l0 - h0, l1 - h1);
                const unsigned long long* wrow =
                    (const unsigned long long*)&sbasis[f0 + j];
#pragma unroll
                for (int k = 0; k < KK; k++) {
                    unsigned long long w = wrow[(size_t)k * 64];
                    fma2(acc[k], w, (k & 1) ? vd : vs);
                }
            }
        }

        // unpack, cepstra to smem (one STS.32 per k), stats reduce
#pragma unroll
        for (int k = 0; k < KK; k++) {
            float c0, c1;
            unpack2(acc[k], c0, c1);

            ((__half2*)&cep[((size_t)z * KK + k) * SPB])[tid] =
                __floats2half2_rn(c0, c1);

            float s = c0 + c1;
            float q = fmaf(c0, c0, c1 * c1);
#pragma unroll
            for (int o = 16; o > 0; o >>= 1) {
                s += __shfl_down_sync(0xffffffffu, s, o);
                q += __shfl_down_sync(0xffffffffu, q, o);
            }
            if (lane == 0) { atomicAdd(&shS[z][k], s); atomicAdd(&shQ[z][k], q); }
        }
    }
    __syncthreads();

    if (tid < 2 * KK) {
        int z = tid / KK, k = tid % KK;
        atomicAdd(&g_sum[z][k],   (double)shS[z][k]);
        atomicAdd(&g_sumsq[z][k], (double)shQ[z][k]);
    }

    // ---------------- grid barrier (grid is fully co-resident) ----------------
    if (tid == 0) {
        __threadfence();
        atomicAdd(&g_arrive, 1u);
        while (*(volatile unsigned*)&g_arrive < GRID1) __nanosleep(64);
        __threadfence();
    }
    __syncthreads();

    // ---------------- finalize normalization (per block, double) --------------
    if (tid < KK) {
        int k = tid;
        double sT = g_sum[0][k], qT = g_sumsq[0][k];
        double sP = g_sum[1][k], qP = g_sumsq[1][k];
        double mT = sT / (double)NN;
        double vT = (qT - sT * sT / (double)NN) / (double)(NN - 1);
        if (vT < 0.0) vT = 0.0;
        double rT = 1.0 / (sqrt(vT) + 1e-6);
        double mP = sP / (double)NN;
        double vP = (qP - sP * sP / (double)NN) / (double)(NN - 1);
        if (vP < 0.0) vP = 0.0;
        double rP = 1.0 / (sqrt(vP) + 1e-6);
        srT[k]  = (float)rT;
        srP[k]  = (float)rP;
        soff[k] = (float)(mT * rT - mP * rP);
    }
    __syncthreads();

    // ---------------- phase 2: MCD from smem cepstra ---------------------------
    float s0 = 0.f, s1 = 0.f;
#pragma unroll
    for (int k = 0; k < KK; k++) {
        float2 t0 = __half22float2(((const __half2*)&cep[((size_t)0 * KK + k) * SPB])[tid]);
        float2 p0 = __half22float2(((const __half2*)&cep[((size_t)1 * KK + k) * SPB])[tid]);
        float rT = srT[k], rP = srP[k], of = soff[k];
        float d0 = fmaf(t0.x, rT, -of) - p0.x * rP;
        float d1 = fmaf(t0.y, rT, -of) - p0.y * rP;
        s0 = fmaf(d0, d0, s0);
        s1 = fmaf(d1, d1, s1);
    }
    float acc = sqrtf(2.0f * s0) + sqrtf(2.0f * s1);

#pragma unroll
    for (int o = 16; o > 0; o >>= 1) acc += __shfl_down_sync(0xffffffffu, acc, o);
    if (lane == 0) atomicAdd(&sh_acc, acc);
    __syncthreads();

    if (tid == 0) {
        atomicAdd(&g_mcd_acc, (double)sh_acc);
        __threadfence();
        unsigned done = atomicAdd(&g_depart, 1u);
        if (done == GRID1 - 1) {
            double total = atomicAdd(&g_mcd_acc, 0.0);
            out[0] = (float)(total * 4.342944819032518 / (double)NN);  // 10/ln10, /N
            // reset ALL persistent state for the next graph replay
            for (int k = 0; k < KK; k++) {
                g_sum[0][k] = 0.0; g_sum[1][k] = 0.0;
                g_sumsq[0][k] = 0.0; g_sumsq[1][k] = 0.0;
            }
            g_mcd_acc = 0.0;
            __threadfence();
            g_arrive = 0u;
            g_depart = 0u;
        }
    }
}

extern "C" void kernel_launch(void* const* d_in, const int* in_sizes, int n_in,
                              void* d_out, int out_size) {
    const float* mel_true = (const float*)d_in[0];
    const float* mel_pred = (const float*)d_in[1];
    float* out = (float*)d_out;

    static bool attr_set = false;
    if (!attr_set) {
        cudaFuncSetAttribute(mcd_fused,
                             cudaFuncAttributeMaxDynamicSharedMemorySize,
                             SMEM_TOTAL);
        attr_set = true;
    }

    mcd_fused<<<GRID1, 512, SMEM_TOTAL>>>(mel_true, mel_pred, out);
}

// round 16
// speedup vs baseline: 1.0025x; 1.0025x over previous
#include <cuda_runtime.h>
#include <cuda_fp16.h>
#include <math.h>

// Problem dims (fixed by reference setup_inputs)
#define BB 64
#define FF 128
#define TT 4096
#define KK 13
#define NN (BB*TT)     // 262144 samples per coefficient
#define T2W (TT/2)     // float2 units along T

#define GRID1 256      // persistent grid: must be <= co-resident capacity (296)
#define SPB   1024     // samples per block (2 per thread, 512 threads)

// ---- device scratch (static: no allocation allowed; zero-init at load) ----
__device__ double   g_sum[2][KK];
__device__ double   g_sumsq[2][KK];
__device__ double   g_mcd_acc;
__device__ unsigned g_arrive;
__device__ unsigned g_depart;

// ---- packed fp32x2 helpers (Blackwell FFMA2 via PTX) ----
__device__ __forceinline__ unsigned long long pack2(float x, float y) {
    unsigned long long r;
    asm("mov.b64 %0, {%1, %2};" : "=l"(r) : "f"(x), "f"(y));
    return r;
}
__device__ __forceinline__ void unpack2(unsigned long long v, float& x, float& y) {
    asm("mov.b64 {%0, %1}, %2;" : "=f"(x), "=f"(y) : "l"(v));
}
__device__ __forceinline__ void fma2(unsigned long long& a,
                                     unsigned long long w,
                                     unsigned long long v) {
    asm("fma.rn.f32x2 %0, %1, %2, %0;" : "+l"(a) : "l"(w), "l"(v));
}

// Dynamic smem layout:
//   [0, 6656)        float2 basis[KK][64]   ({w,w} pairs, ln2+scale folded)
//   [6656, 59904)    __half cep[2][KK][SPB] (per-block cepstra, both tensors)
#define SMEM_BASIS 0
#define SMEM_CEP   6656
#define SMEM_TOTAL 59904

// ---------------------------------------------------------------------------
// Persistent fused kernel (512 threads, 2 samples/thread for low regs + 32
// warps/SM on doubly-occupied SMs):
//  phase 1: log2(1+|x|) -> folded 13-pt DCT (f32x2 FMAs) for both tensors,
//           cepstra -> SMEM (fp16), stats -> global double atomics
//  grid barrier (arrive counter + spin; grid fully co-resident)
//  phase 2: finalize mean/rstd per block, MCD from SMEM cepstra, last block
//           writes the scalar and resets all global state for graph replay.
// Block bx: b = bx>>2, t-chunk = bx&3. Thread owns 2 adjacent t (float2).
// ---------------------------------------------------------------------------
__global__ __launch_bounds__(512, 2) void mcd_fused(const float* __restrict__ xt,
                                                    const float* __restrict__ xp,
                                                    float* __restrict__ out) {
    extern __shared__ char dsm[];
    float2* sbasis = (float2*)(dsm + SMEM_BASIS);          // [KK][64]
    __half* cep    = (__half*)(dsm + SMEM_CEP);            // [2][KK][SPB]

    __shared__ float shS[2][KK], shQ[2][KK];
    __shared__ float srT[KK], srP[KK], soff[KK];
    __shared__ float sh_acc;

    const int tid = threadIdx.x;

    // build basis: {w,w} duplicated, dct scale and ln2 folded in
    for (int i = tid; i < KK * 64; i += blockDim.x) {
        int k = i >> 6, f = i & 63;
        float scale = (k == 0) ? 0.088388347648318447f : 0.125f;
        float w = cospif((float)((2*f + 1) * k) * (1.0f/256.0f))
                * scale * 0.69314718055994531f;
        sbasis[i] = make_float2(w, w);
    }
    if (tid < 2 * KK) {
        ((float*)shS)[tid] = 0.f;
        ((float*)shQ)[tid] = 0.f;
    }
    if (tid == 0) sh_acc = 0.f;
    __syncthreads();

    const int b  = blockIdx.x >> 2;
    const int tc = blockIdx.x & 3;
    const int t2 = tc * 512 + tid;          // float2 index along T
    const int lane = tid & 31;

    // ---------------- phase 1: DCT + stats, cepstra to smem ----------------
#pragma unroll 1
    for (int z = 0; z < 2; z++) {
        const float* src = z ? xp : xt;
        const float2* px = (const float2*)(src + (size_t)b * FF * TT) + t2;

        unsigned long long acc[KK];   // packed (c_lo, c_hi) fp32 pairs
#pragma unroll
        for (int k = 0; k < KK; k++) acc[k] = 0ull;

        const int PF = 4;
        float2 bl[PF], bh[PF];
#pragma unroll
        for (int j = 0; j < PF; j++) {
            bl[j] = __ldcs(px + (size_t)j * T2W);
            bh[j] = __ldcs(px + (size_t)(FF-1-j) * T2W);
        }

#pragma unroll 1
        for (int f0 = 0; f0 < 64; f0 += PF) {
            float2 cl[PF], ch[PF];
#pragma unroll
            for (int j = 0; j < PF; j++) { cl[j] = bl[j]; ch[j] = bh[j]; }
            if (f0 + PF < 64) {
#pragma unroll
                for (int j = 0; j < PF; j++) {
                    bl[j] = __ldcs(px + (size_t)(f0 + PF + j) * T2W);
                    bh[j] = __ldcs(px + (size_t)(FF-1 - (f0 + PF + j)) * T2W);
                }
            }
#pragma unroll
            for (int j = 0; j < PF; j++) {
                float l0 = __log2f(1.0f + fabsf(cl[j].x));
                float l1 = __log2f(1.0f + fabsf(cl[j].y));
                float h0 = __log2f(1.0f + fabsf(ch[j].x));
                float h1 = __log2f(1.0f + fabsf(ch[j].y));
                unsigned long long vs = pack2(l0 + h0, l1 + h1);
                unsigned long long vd = pack2(l0 - h0, l1 - h1);
                const unsigned long long* wrow =
                    (const unsigned long long*)&sbasis[f0 + j];
#pragma unroll
                for (int k = 0; k < KK; k++) {
                    unsigned long long w = wrow[(size_t)k * 64];
                    fma2(acc[k], w, (k & 1) ? vd : vs);
                }
            }
        }

        // unpack, cepstra to smem (one STS.32 per k), stats reduce
#pragma unroll
        for (int k = 0; k < KK; k++) {
            float c0, c1;
            unpack2(acc[k], c0, c1);

            ((__half2*)&cep[((size_t)z * KK + k) * SPB])[tid] =
                __floats2half2_rn(c0, c1);

            float s = c0 + c1;
            float q = fmaf(c0, c0, c1 * c1);
#pragma unroll
            for (int o = 16; o > 0; o >>= 1) {
                s += __shfl_down_sync(0xffffffffu, s, o);
                q += __shfl_down_sync(0xffffffffu, q, o);
            }
            if (lane == 0) { atomicAdd(&shS[z][k], s); atomicAdd(&shQ[z][k], q); }
        }
    }
    __syncthreads();

    if (tid < 2 * KK) {
        int z = tid / KK, k = tid % KK;
        atomicAdd(&g_sum[z][k],   (double)shS[z][k]);
        atomicAdd(&g_sumsq[z][k], (double)shQ[z][k]);
    }

    // ---------------- grid barrier (grid is fully co-resident) ----------------
    if (tid == 0) {
        __threadfence();
        atomicAdd(&g_arrive, 1u);
        while (*(volatile unsigned*)&g_arrive < GRID1) __nanosleep(64);
        __threadfence();
    }
    __syncthreads();

    // ---------------- finalize normalization (per block, double) --------------
    if (tid < KK) {
        int k = tid;
        double sT = g_sum[0][k], qT = g_sumsq[0][k];
        double sP = g_sum[1][k], qP = g_sumsq[1][k];
        double mT = sT / (double)NN;
        double vT = (qT - sT * sT / (double)NN) / (double)(NN - 1);
        if (vT < 0.0) vT = 0.0;
        double rT = 1.0 / (sqrt(vT) + 1e-6);
        double mP = sP / (double)NN;
        double vP = (qP - sP * sP / (double)NN) / (double)(NN - 1);
        if (vP < 0.0) vP = 0.0;
        double rP = 1.0 / (sqrt(vP) + 1e-6);
        srT[k]  = (float)rT;
        srP[k]  = (float)rP;
        soff[k] = (float)(mT * rT - mP * rP);
    }
    __syncthreads();

    // ---------------- phase 2: MCD from smem cepstra ---------------------------
    float s0 = 0.f, s1 = 0.f;
#pragma unroll
    for (int k = 0; k < KK; k++) {
        float2 t0 = __half22float2(((const __half2*)&cep[((size_t)0 * KK + k) * SPB])[tid]);
        float2 p0 = __half22float2(((const __half2*)&cep[((size_t)1 * KK + k) * SPB])[tid]);
        float rT = srT[k], rP = srP[k], of = soff[k];
        float d0 = fmaf(t0.x, rT, -of) - p0.x * rP;
        float d1 = fmaf(t0.y, rT, -of) - p0.y * rP;
        s0 = fmaf(d0, d0, s0);
        s1 = fmaf(d1, d1, s1);
    }
    float acc = sqrtf(2.0f * s0) + sqrtf(2.0f * s1);

#pragma unroll
    for (int o = 16; o > 0; o >>= 1) acc += __shfl_down_sync(0xffffffffu, acc, o);
    if (lane == 0) atomicAdd(&sh_acc, acc);
    __syncthreads();

    if (tid == 0) {
        atomicAdd(&g_mcd_acc, (double)sh_acc);
        __threadfence();
        unsigned done = atomicAdd(&g_depart, 1u);
        if (done == GRID1 - 1) {
            double total = atomicAdd(&g_mcd_acc, 0.0);
            out[0] = (float)(total * 4.342944819032518 / (double)NN);  // 10/ln10, /N
            // reset ALL persistent state for the next graph replay
            for (int k = 0; k < KK; k++) {
                g_sum[0][k] = 0.0; g_sum[1][k] = 0.0;
                g_sumsq[0][k] = 0.0; g_sumsq[1][k] = 0.0;
            }
            g_mcd_acc = 0.0;
            __threadfence();
            g_arrive = 0u;
            g_depart = 0u;
        }
    }
}

extern "C" void kernel_launch(void* const* d_in, const int* in_sizes, int n_in,
                              void* d_out, int out_size) {
    const float* mel_true = (const float*)d_in[0];
    const float* mel_pred = (const float*)d_in[1];
    float* out = (float*)d_out;

    static bool attr_set = false;
    if (!attr_set) {
        cudaFuncSetAttribute(mcd_fused,
                             cudaFuncAttributeMaxDynamicSharedMemorySize,
                             SMEM_TOTAL);
        attr_set = true;
    }

    mcd_fused<<<GRID1, 512, SMEM_TOTAL>>>(mel_true, mel_pred, out);
}

// round 17
// speedup vs baseline: 1.6653x; 1.6612x over previous
#include <cuda_runtime.h>
#include <cuda_fp16.h>
#include <math.h>

// Problem dims (fixed by reference setup_inputs)
#define BB 64
#define FF 128
#define TT 4096
#define KK 13
#define NN (BB*TT)     // 262144 samples per coefficient
#define T4 (TT/4)      // float4 units along T

#define GRID1 256      // persistent grid: must be <= co-resident capacity (296)
#define SPB   1024     // samples per block (4 per thread, 256 threads)
#define NST   6        // cp.async pipeline stages (f-pairs in flight)

// ---- device scratch (static: no allocation allowed; zero-init at load) ----
__device__ double   g_sum[2][KK];
__device__ double   g_sumsq[2][KK];
__device__ double   g_mcd_acc;
__device__ unsigned g_arrive;
__device__ unsigned g_depart;

// ---- packed fp32x2 helpers (Blackwell FFMA2 via PTX) ----
__device__ __forceinline__ unsigned long long pack2(float x, float y) {
    unsigned long long r;
    asm("mov.b64 %0, {%1, %2};" : "=l"(r) : "f"(x), "f"(y));
    return r;
}
__device__ __forceinline__ void unpack2(unsigned long long v, float& x, float& y) {
    asm("mov.b64 {%0, %1}, %2;" : "=f"(x), "=f"(y) : "l"(v));
}
__device__ __forceinline__ void fma2(unsigned long long& a,
                                     unsigned long long w,
                                     unsigned long long v) {
    asm("fma.rn.f32x2 %0, %1, %2, %0;" : "+l"(a) : "l"(w), "l"(v));
}

// ---- cp.async helpers ----
__device__ __forceinline__ void cpa16(unsigned smem_addr, const void* gptr) {
    asm volatile("cp.async.cg.shared.global [%0], [%1], 16;"
                 :: "r"(smem_addr), "l"(gptr));
}
__device__ __forceinline__ void cpa_commit() {
    asm volatile("cp.async.commit_group;");
}
template <int N>
__device__ __forceinline__ void cpa_wait() {
    asm volatile("cp.async.wait_group %0;" :: "n"(N));
}

// Dynamic smem layout (bytes):
//   [0, 6656)            float2 basis[KK][64]  ({w,w} pairs, ln2+scale folded)
//   [6656, 55808)        staging: NST stages x (256 thr x {low16B, high16B})
//                        stage s: low  at 6656 + s*8192 + tid*16
//                                 high at 6656 + s*8192 + 4096 + tid*16
//   [55808, 109056)      __half cep[2][KK][SPB]
#define SMEM_BASIS 0
#define SMEM_STAGE 6656
#define STAGE_BYTES 8192
#define SMEM_CEP   (SMEM_STAGE + NST * STAGE_BYTES)       // 55808
#define SMEM_TOTAL (SMEM_CEP + 2 * KK * SPB * 2)          // 109056

// ---------------------------------------------------------------------------
// Persistent fused kernel (256 threads, 4 samples/thread, float4 everywhere):
//  phase 1: cp.async 6-stage input pipeline -> log2(1+|x|) -> folded 13-pt
//           DCT (f32x2 FMAs) for both tensors; cepstra -> SMEM (fp16);
//           stats -> global double atomics
//  grid barrier (arrive counter + spin; grid fully co-resident: 256 <= 296)
//  phase 2: finalize mean/rstd per block, MCD from SMEM cepstra, last block
//           writes the scalar and resets all global state for graph replay.
// Block bx: b = bx>>2, t-chunk = bx&3. Thread owns 4 consecutive t (float4).
// Staging is thread-private (each thread reads only what it copied), so no
// __syncthreads() in the pipeline — only cp.async.wait_group.
// ---------------------------------------------------------------------------
__global__ __launch_bounds__(256, 2) void mcd_fused(const float* __restrict__ xt,
                                                    const float* __restrict__ xp,
                                                    float* __restrict__ out) {
    extern __shared__ char dsm[];
    float2* sbasis = (float2*)(dsm + SMEM_BASIS);          // [KK][64]
    __half* cep    = (__half*)(dsm + SMEM_CEP);            // [2][KK][SPB]

    __shared__ float shS[2][KK], shQ[2][KK];
    __shared__ float srT[KK], srP[KK], soff[KK];
    __shared__ float sh_acc;

    const int tid = threadIdx.x;

    // build basis: {w,w} duplicated, dct scale and ln2 folded in
    for (int i = tid; i < KK * 64; i += blockDim.x) {
        int k = i >> 6, f = i & 63;
        float scale = (k == 0) ? 0.088388347648318447f : 0.125f;
        float w = cospif((float)((2*f + 1) * k) * (1.0f/256.0f))
                * scale * 0.69314718055994531f;
        sbasis[i] = make_float2(w, w);
    }
    if (tid < 2 * KK) {
        ((float*)shS)[tid] = 0.f;
        ((float*)shQ)[tid] = 0.f;
    }
    if (tid == 0) sh_acc = 0.f;
    __syncthreads();

    const int b  = blockIdx.x >> 2;
    const int tc = blockIdx.x & 3;
    const int t4 = tc * 256 + tid;          // float4 index along T
    const int lane = tid & 31;

    // thread-private staging slots (byte offsets into dsm / shared address)
    const unsigned stage_u32 =
        (unsigned)__cvta_generic_to_shared(dsm + SMEM_STAGE) + tid * 16;
    char* stage_gen = dsm + SMEM_STAGE + tid * 16;

    // ---------------- phase 1: DCT + stats, cepstra to smem ----------------
#pragma unroll 1
    for (int z = 0; z < 2; z++) {
        const float* src = z ? xp : xt;
        const float4* px = (const float4*)(src + (size_t)b * FF * TT) + t4;

        unsigned long long a01[KK], a23[KK];   // packed accum pairs (s0,s1),(s2,s3)
#pragma unroll
        for (int k = 0; k < KK; k++) { a01[k] = 0ull; a23[k] = 0ull; }

        // pipeline prologue: fill all NST stages
#pragma unroll
        for (int j = 0; j < NST; j++) {
            cpa16(stage_u32 + j * STAGE_BYTES,        px + (size_t)j * T4);
            cpa16(stage_u32 + j * STAGE_BYTES + 4096, px + (size_t)(FF-1-j) * T4);
            cpa_commit();
        }

#pragma unroll 1
        for (int i = 0; i < 64; i++) {
            cpa_wait<NST - 1>();               // stage for f-pair i is ready
            const int s = i % NST;
            float4 lo = *(const float4*)(stage_gen + s * STAGE_BYTES);
            float4 hi = *(const float4*)(stage_gen + s * STAGE_BYTES + 4096);

            // refill this stage with f-pair i+NST (or commit empty group)
            const int fn = i + NST;
            if (fn < 64) {
                cpa16(stage_u32 + s * STAGE_BYTES,        px + (size_t)fn * T4);
                cpa16(stage_u32 + s * STAGE_BYTES + 4096, px + (size_t)(FF-1-fn) * T4);
            }
            cpa_commit();

            float l0 = __log2f(1.0f + fabsf(lo.x));
            float l1 = __log2f(1.0f + fabsf(lo.y));
            float l2 = __log2f(1.0f + fabsf(lo.z));
            float l3 = __log2f(1.0f + fabsf(lo.w));
            float h0 = __log2f(1.0f + fabsf(hi.x));
            float h1 = __log2f(1.0f + fabsf(hi.y));
            float h2 = __log2f(1.0f + fabsf(hi.z));
            float h3 = __log2f(1.0f + fabsf(hi.w));
            unsigned long long vs01 = pack2(l0 + h0, l1 + h1);
            unsigned long long vs23 = pack2(l2 + h2, l3 + h3);
            unsigned long long vd01 = pack2(l0 - h0, l1 - h1);
            unsigned long long vd23 = pack2(l2 - h2, l3 - h3);
            const unsigned long long* wrow =
                (const unsigned long long*)&sbasis[i];
#pragma unroll
            for (int k = 0; k < KK; k++) {
                unsigned long long w = wrow[(size_t)k * 64];
                if (k & 1) { fma2(a01[k], w, vd01); fma2(a23[k], w, vd23); }
                else       { fma2(a01[k], w, vs01); fma2(a23[k], w, vs23); }
            }
        }

        // unpack, cepstra to smem, stats reduce
#pragma unroll
        for (int k = 0; k < KK; k++) {
            float c0, c1, c2, c3;
            unpack2(a01[k], c0, c1);
            unpack2(a23[k], c2, c3);

            __half2* dstp = (__half2*)&cep[((size_t)z * KK + k) * SPB + tid * 4];
            dstp[0] = __floats2half2_rn(c0, c1);
            dstp[1] = __floats2half2_rn(c2, c3);

            float s = (c0 + c1) + (c2 + c3);
            float q = fmaf(c0, c0, c1 * c1) + fmaf(c2, c2, c3 * c3);
#pragma unroll
            for (int o = 16; o > 0; o >>= 1) {
                s += __shfl_down_sync(0xffffffffu, s, o);
                q += __shfl_down_sync(0xffffffffu, q, o);
            }
            if (lane == 0) { atomicAdd(&shS[z][k], s); atomicAdd(&shQ[z][k], q); }
        }
    }
    __syncthreads();

    if (tid < 2 * KK) {
        int z = tid / KK, k = tid % KK;
        atomicAdd(&g_sum[z][k],   (double)shS[z][k]);
        atomicAdd(&g_sumsq[z][k], (double)shQ[z][k]);
    }

    // ---------------- grid barrier (grid is fully co-resident) ----------------
    if (tid == 0) {
        __threadfence();
        atomicAdd(&g_arrive, 1u);
        while (*(volatile unsigned*)&g_arrive < GRID1) __nanosleep(64);
        __threadfence();
    }
    __syncthreads();

    // ---------------- finalize normalization (per block, double) --------------
    if (tid < KK) {
        int k = tid;
        double sT = g_sum[0][k], qT = g_sumsq[0][k];
        double sP = g_sum[1][k], qP = g_sumsq[1][k];
        double mT = sT / (double)NN;
        double vT = (qT - sT * sT / (double)NN) / (double)(NN - 1);
        if (vT < 0.0) vT = 0.0;
        double rT = 1.0 / (sqrt(vT) + 1e-6);
        double mP = sP / (double)NN;
        double vP = (qP - sP * sP / (double)NN) / (double)(NN - 1);
        if (vP < 0.0) vP = 0.0;
        double rP = 1.0 / (sqrt(vP) + 1e-6);
        srT[k]  = (float)rT;
        srP[k]  = (float)rP;
        soff[k] = (float)(mT * rT - mP * rP);
    }
    __syncthreads();

    // ---------------- phase 2: MCD from smem cepstra ---------------------------
    float s0 = 0.f, s1 = 0.f, s2 = 0.f, s3 = 0.f;
#pragma unroll
    for (int k = 0; k < KK; k++) {
        const __half2* pT = (const __half2*)&cep[((size_t)0 * KK + k) * SPB + tid * 4];
        const __half2* pP = (const __half2*)&cep[((size_t)1 * KK + k) * SPB + tid * 4];
        float2 t0 = __half22float2(pT[0]);
        float2 t1 = __half22float2(pT[1]);
        float2 p0 = __half22float2(pP[0]);
        float2 p1 = __half22float2(pP[1]);
        float rT = srT[k], rP = srP[k], of = soff[k];
        float d0 = fmaf(t0.x, rT, -of) - p0.x * rP;
        float d1 = fmaf(t0.y, rT, -of) - p0.y * rP;
        float d2 = fmaf(t1.x, rT, -of) - p1.x * rP;
        float d3 = fmaf(t1.y, rT, -of) - p1.y * rP;
        s0 = fmaf(d0, d0, s0);
        s1 = fmaf(d1, d1, s1);
        s2 = fmaf(d2, d2, s2);
        s3 = fmaf(d3, d3, s3);
    }
    float acc = (sqrtf(2.0f * s0) + sqrtf(2.0f * s1))
              + (sqrtf(2.0f * s2) + sqrtf(2.0f * s3));

#pragma unroll
    for (int o = 16; o > 0; o >>= 1) acc += __shfl_down_sync(0xffffffffu, acc, o);
    if (lane == 0) atomicAdd(&sh_acc, acc);
    __syncthreads();

    if (tid == 0) {
        atomicAdd(&g_mcd_acc, (double)sh_acc);
        __threadfence();
        unsigned done = atomicAdd(&g_depart, 1u);
        if (done == GRID1 - 1) {
            double total = atomicAdd(&g_mcd_acc, 0.0);
            out[0] = (float)(total * 4.342944819032518 / (double)NN);  // 10/ln10, /N
            // reset ALL persistent state for the next graph replay
            for (int k = 0; k < KK; k++) {
                g_sum[0][k] = 0.0; g_sum[1][k] = 0.0;
                g_sumsq[0][k] = 0.0; g_sumsq[1][k] = 0.0;
            }
            g_mcd_acc = 0.0;
            __threadfence();
            g_arrive = 0u;
            g_depart = 0u;
        }
    }
}

extern "C" void kernel_launch(void* const* d_in, const int* in_sizes, int n_in,
                              void* d_out, int out_size) {
    const float* mel_true = (const float*)d_in[0];
    const float* mel_pred = (const float*)d_in[1];
    float* out = (float*)d_out;

    static bool attr_set = false;
    if (!attr_set) {
        cudaFuncSetAttribute(mcd_fused,
                             cudaFuncAttributeMaxDynamicSharedMemorySize,
                             SMEM_TOTAL);
        attr_set = true;
    }

    mcd_fused<<<GRID1, 256, SMEM_TOTAL>>>(mel_true, mel_pred, out);
}